// round 7
// baseline (speedup 1.0000x reference)
#include <cuda_runtime.h>
#include <cuda_bf16.h>
#include <math.h>
#include <stdint.h>

#define CB  128
#define CIN 256
#define NSP 4096
#define NB  4

typedef unsigned long long u64;

// ===================== helpers =====================
__device__ __forceinline__ uint32_t smem_to_u32(const void* p) {
    uint32_t a;
    asm("{ .reg .u64 t; cvta.to.shared.u64 t, %1; cvt.u32.u64 %0, t; }" : "=r"(a) : "l"(p));
    return a;
}
__device__ __forceinline__ void ldsm4(uint32_t* r, uint32_t a) {
    asm volatile("ldmatrix.sync.aligned.m8n8.x4.shared.b16 {%0,%1,%2,%3}, [%4];"
        : "=r"(r[0]), "=r"(r[1]), "=r"(r[2]), "=r"(r[3]) : "r"(a));
}
__device__ __forceinline__ void mma16816(float* c, const uint32_t* a, uint32_t b0, uint32_t b1) {
    asm volatile("mma.sync.aligned.m16n8k16.row.col.f32.bf16.bf16.f32 "
        "{%0,%1,%2,%3}, {%4,%5,%6,%7}, {%8,%9}, {%0,%1,%2,%3};"
        : "+f"(c[0]), "+f"(c[1]), "+f"(c[2]), "+f"(c[3])
        : "r"(a[0]), "r"(a[1]), "r"(a[2]), "r"(a[3]), "r"(b0), "r"(b1));
}
// FFMA2 helpers (SIMT kernels)
__device__ __forceinline__ u64 pk2(float a, float b) {
    u64 r; asm("mov.b64 %0, {%1, %2};" : "=l"(r) : "f"(a), "f"(b)); return r;
}
__device__ __forceinline__ void upk2(u64 v, float& a, float& b) {
    asm("mov.b64 {%0, %1}, %2;" : "=f"(a), "=f"(b) : "l"(v));
}
__device__ __forceinline__ u64 fma2(u64 a, u64 b, u64 c) {
    u64 d; asm("fma.rn.f32x2 %0, %1, %2, %3;" : "=l"(d) : "l"(a), "l"(b), "l"(c)); return d;
}

// ===================== scratch =====================
__device__ float g_T[(size_t)NB * CB * NSP];
__device__ float g_P[(size_t)NB * CB * NSP];
__device__ float g_G[(size_t)NB * CB * NSP];
__device__ float g_Y[(size_t)NB * CB * NSP];
__device__ float g_S[(size_t)NB * NSP * NSP];          // expS fp32
__device__ float g_Zp[NB * 32 * NSP];
__device__ float g_Zr[NB * NSP];
__device__ __nv_bfloat16 g_Thi[(size_t)NB * NSP * CB]; // (n,k)
__device__ __nv_bfloat16 g_Tlo[(size_t)NB * NSP * CB];
__device__ __nv_bfloat16 g_Phi[(size_t)NB * NSP * CB]; // Pt (n,k)
__device__ __nv_bfloat16 g_Plo[(size_t)NB * NSP * CB];
__device__ __nv_bfloat16 g_Ghi[(size_t)NB * CB * NSP]; // Gt' (c,m), scaled by 1/Z
__device__ __nv_bfloat16 g_Glo[(size_t)NB * CB * NSP];

// SMEM layouts (row stride 272B = 136 bf16: 272 mod 128 = 16 -> conflict-free ldmatrix)
#define SC_AHI 0
#define SC_ALO 34816
#define SC_BHI 69632
#define SC_BLO 104448
#define SC_BYTES 139264

#define Y_AHI 0
#define Y_ALO 17408
#define Y_BHI 34816
#define Y_BLO 69632
#define Y_BYTES 104448

// ---------------------------------------------------------------------------
// Kernel 1: T/P/G 1x1 convs (SIMT FFMA2). grid (32,1,12)
// ---------------------------------------------------------------------------
__global__ __launch_bounds__(256, 2) void conv_tpg_kernel(
    const float* __restrict__ x,
    const float* __restrict__ tw, const float* __restrict__ tbias,
    const float* __restrict__ pw, const float* __restrict__ pbias,
    const float* __restrict__ gw, const float* __restrict__ gbias)
{
    int z = blockIdx.z;
    int b = z / 3, mat = z - b * 3;
    const float* W    = (mat == 0) ? tw    : (mat == 1) ? pw    : gw;
    const float* bias = (mat == 0) ? tbias : (mat == 1) ? pbias : gbias;
    float* Cout = ((mat == 0) ? g_T : (mat == 1) ? g_P : g_G) + (size_t)b * CB * NSP;
    const float* Bx = x + (size_t)b * CIN * NSP;

    __shared__ __align__(16) float As[8][132];
    __shared__ __align__(16) float Bs[8][128];
    int tid  = threadIdx.x;
    int aRow = tid >> 1, aCol = (tid & 1) << 2;
    int bRow = tid >> 5, bCol = (tid & 31) << 2;
    int ty = tid >> 4, tx = tid & 15;
    int colBase = blockIdx.x << 7;

    u64 acc[8][4];
#pragma unroll
    for (int i = 0; i < 8; i++)
#pragma unroll
        for (int jp = 0; jp < 4; jp++) acc[i][jp] = pk2(0.f, 0.f);

    for (int k0 = 0; k0 < CIN; k0 += 8) {
        float4 av = *(const float4*)(W + (size_t)aRow * CIN + k0 + aCol);
        As[aCol + 0][aRow] = av.x;
        As[aCol + 1][aRow] = av.y;
        As[aCol + 2][aRow] = av.z;
        As[aCol + 3][aRow] = av.w;
        *(float4*)&Bs[bRow][bCol] =
            *(const float4*)(Bx + (size_t)(k0 + bRow) * NSP + colBase + bCol);
        __syncthreads();
#pragma unroll
        for (int k = 0; k < 8; k++) {
            float ra[8];
            *(float4*)(ra)     = *(const float4*)&As[k][ty << 2];
            *(float4*)(ra + 4) = *(const float4*)&As[k][64 + (ty << 2)];
            const u64* bp0 = (const u64*)&Bs[k][tx << 2];
            const u64* bp1 = (const u64*)&Bs[k][64 + (tx << 2)];
            u64 rb[4] = {bp0[0], bp0[1], bp1[0], bp1[1]};
#pragma unroll
            for (int i = 0; i < 8; i++) {
                u64 aa = pk2(ra[i], ra[i]);
#pragma unroll
                for (int jp = 0; jp < 4; jp++)
                    acc[i][jp] = fma2(aa, rb[jp], acc[i][jp]);
            }
        }
        __syncthreads();
    }
#pragma unroll
    for (int i = 0; i < 8; i++) {
        int row = ((i >> 2) << 6) + (ty << 2) + (i & 3);
        float bv = bias[row];
#pragma unroll
        for (int jh = 0; jh < 2; jh++) {
            float4 v;
            upk2(acc[i][2 * jh],     v.x, v.y);
            upk2(acc[i][2 * jh + 1], v.z, v.w);
            v.x += bv; v.y += bv; v.z += bv; v.w += bv;
            *(float4*)(Cout + (size_t)row * NSP + colBase + (jh << 6) + (tx << 2)) = v;
        }
    }
}

// ---------------------------------------------------------------------------
// Kernel 2a: T -> bf16 hi/lo. grid 2048, 256 thr
// ---------------------------------------------------------------------------
__global__ __launch_bounds__(256) void cvtT_kernel()
{
    size_t i = ((size_t)blockIdx.x * 256 + threadIdx.x) * 4;
    float4 v = *(const float4*)(g_T + i);
    __nv_bfloat16 hx = __float2bfloat16_rn(v.x), hy = __float2bfloat16_rn(v.y);
    __nv_bfloat16 hz = __float2bfloat16_rn(v.z), hw = __float2bfloat16_rn(v.w);
    __nv_bfloat162 h01(hx, hy), h23(hz, hw);
    __nv_bfloat162 l01(__float2bfloat16_rn(v.x - __bfloat162float(hx)),
                       __float2bfloat16_rn(v.y - __bfloat162float(hy)));
    __nv_bfloat162 l23(__float2bfloat16_rn(v.z - __bfloat162float(hz)),
                       __float2bfloat16_rn(v.w - __bfloat162float(hw)));
    *(uint2*)(g_Thi + i) = make_uint2(*(uint32_t*)&h01, *(uint32_t*)&h23);
    *(uint2*)(g_Tlo + i) = make_uint2(*(uint32_t*)&l01, *(uint32_t*)&l23);
}

// ---------------------------------------------------------------------------
// Kernel 2b: P (128,4096) -> Pt (4096,128) bf16 hi/lo. grid (128,4,NB), blk (32,8)
// ---------------------------------------------------------------------------
__global__ __launch_bounds__(256) void trP_kernel()
{
    int b = blockIdx.z;
    const float* P = g_P + (size_t)b * CB * NSP;
    __shared__ float sm[32][33];
    int tx = threadIdx.x, ty = threadIdx.y;
    int n0 = blockIdx.x << 5, k0 = blockIdx.y << 5;
#pragma unroll
    for (int i = 0; i < 4; i++)
        sm[ty + i * 8][tx] = P[(size_t)(k0 + ty + i * 8) * NSP + n0 + tx];
    __syncthreads();
#pragma unroll
    for (int i = 0; i < 4; i++) {
        int n = n0 + ty + i * 8, k = k0 + tx;
        float v = sm[tx][ty + i * 8];
        __nv_bfloat16 h = __float2bfloat16_rn(v);
        g_Phi[((size_t)b * NSP + n) * CB + k] = h;
        g_Plo[((size_t)b * NSP + n) * CB + k] = __float2bfloat16_rn(v - __bfloat162float(h));
    }
}

// ---------------------------------------------------------------------------
// Kernel 3: expS(128x128 tile) = exp( T @ Pt^T ) via mma.sync bf16 3-pass
// grid (32 coltile, 32 rowtile, NB), 256 thr (8 warps, 32x64 warp tiles)
// ---------------------------------------------------------------------------
__global__ __launch_bounds__(256, 1) void scores_mma_kernel()
{
    extern __shared__ __align__(16) char smem[];
    const int tid = threadIdx.x;
    const int wid = tid >> 5, lane = tid & 31;
    const int b = blockIdx.z;
    const int rowBase = blockIdx.y << 7;
    const int colBase = blockIdx.x << 7;

    {   // stage A (T rows) and B (Pt rows) hi/lo, row stride 272B
        const __nv_bfloat16* Ah = g_Thi + ((size_t)b * NSP + rowBase) * CB;
        const __nv_bfloat16* Al = g_Tlo + ((size_t)b * NSP + rowBase) * CB;
        const __nv_bfloat16* Bh = g_Phi + ((size_t)b * NSP + colBase) * CB;
        const __nv_bfloat16* Bl = g_Plo + ((size_t)b * NSP + colBase) * CB;
        int r = tid >> 1, half = tid & 1;
#pragma unroll
        for (int j = 0; j < 8; j++) {
            int k = half * 64 + j * 8;
            size_t gi = (size_t)r * CB + k;
            uint32_t so = r * 272 + k * 2;
            *(uint4*)(smem + SC_AHI + so) = *(const uint4*)(Ah + gi);
            *(uint4*)(smem + SC_ALO + so) = *(const uint4*)(Al + gi);
            *(uint4*)(smem + SC_BHI + so) = *(const uint4*)(Bh + gi);
            *(uint4*)(smem + SC_BLO + so) = *(const uint4*)(Bl + gi);
        }
    }
    __syncthreads();

    const uint32_t sb = smem_to_u32(smem);
    const int mrow = (wid >> 1) * 32, ncol = (wid & 1) * 64;
    const int aR = lane & 15, aK = (lane >> 4) * 8;
    const int bN = (lane & 7) + ((lane >> 4) << 3), bK = ((lane >> 3) & 1) * 8;

    float acc[2][8][4];
#pragma unroll
    for (int mi = 0; mi < 2; mi++)
#pragma unroll
        for (int n = 0; n < 8; n++)
#pragma unroll
            for (int q = 0; q < 4; q++) acc[mi][n][q] = 0.f;

#pragma unroll
    for (int ks = 0; ks < 8; ks++) {
        int k0 = ks * 16;
        uint32_t ahi[2][4], alo[2][4];
#pragma unroll
        for (int mi = 0; mi < 2; mi++) {
            uint32_t ad = sb + SC_AHI + (mrow + mi * 16 + aR) * 272 + (k0 + aK) * 2;
            ldsm4(ahi[mi], ad);
            ldsm4(alo[mi], ad + (SC_ALO - SC_AHI));
        }
#pragma unroll
        for (int nj = 0; nj < 4; nj++) {
            uint32_t bhi[4], blo[4];
            uint32_t bd = sb + SC_BHI + (ncol + nj * 16 + bN) * 272 + (k0 + bK) * 2;
            ldsm4(bhi, bd);
            ldsm4(blo, bd + (SC_BLO - SC_BHI));
#pragma unroll
            for (int mi = 0; mi < 2; mi++) {
                mma16816(acc[mi][nj * 2],     ahi[mi], bhi[0], bhi[1]);
                mma16816(acc[mi][nj * 2 + 1], ahi[mi], bhi[2], bhi[3]);
                mma16816(acc[mi][nj * 2],     ahi[mi], blo[0], blo[1]);
                mma16816(acc[mi][nj * 2 + 1], ahi[mi], blo[2], blo[3]);
                mma16816(acc[mi][nj * 2],     alo[mi], bhi[0], bhi[1]);
                mma16816(acc[mi][nj * 2 + 1], alo[mi], bhi[2], bhi[3]);
            }
        }
    }
    __syncthreads();   // tiles no longer needed; reuse smem for column reduction

    float (*sRed)[129] = (float(*)[129])smem;
    float* Sout = g_S + (size_t)b * NSP * NSP;
    const int g = lane >> 2, tig = lane & 3;
#pragma unroll
    for (int mi = 0; mi < 2; mi++)
#pragma unroll
        for (int rr = 0; rr < 2; rr++) {
            int rowl = mrow + mi * 16 + g + rr * 8;
            float* orow = Sout + (size_t)(rowBase + rowl) * NSP + colBase;
#pragma unroll
            for (int ni = 0; ni < 8; ni++) {
                int coll = ncol + ni * 8 + tig * 2;
                float e0 = __expf(acc[mi][ni][rr * 2 + 0]);
                float e1 = __expf(acc[mi][ni][rr * 2 + 1]);
                *(float2*)(orow + coll) = make_float2(e0, e1);
                sRed[rowl][coll]     = e0;
                sRed[rowl][coll + 1] = e1;
            }
        }
    __syncthreads();
    if (tid < 128) {
        float s = 0.f;
#pragma unroll 16
        for (int r = 0; r < 128; r++) s += sRed[r][tid];
        g_Zp[(b * 32 + blockIdx.y) * NSP + colBase + tid] = s;
    }
}

// ---------------------------------------------------------------------------
// Kernel 4: 1/Z per column. grid 64, 256 thr
// ---------------------------------------------------------------------------
__global__ __launch_bounds__(256) void zreduce_kernel()
{
    int t = blockIdx.x * 256 + threadIdx.x;
    int b = t >> 12, m = t & (NSP - 1);
    float s = 0.f;
#pragma unroll 8
    for (int r = 0; r < 32; r++) s += g_Zp[(b * 32 + r) * NSP + m];
    g_Zr[t] = 1.0f / s;
}

// ---------------------------------------------------------------------------
// Kernel 5: Gt'(c,m) = Gview[m][c] * Zr[m], bf16 hi/lo. grid (128,4,NB), blk (32,8)
// ---------------------------------------------------------------------------
__global__ __launch_bounds__(256) void gscale_kernel()
{
    int b = blockIdx.z;
    const float* Gf = g_G + (size_t)b * CB * NSP;   // flat view (m, c) ld=CB
    const float* Zr = g_Zr + b * NSP;
    __shared__ float sm[32][33];
    int tx = threadIdx.x, ty = threadIdx.y;
    int m0 = blockIdx.x << 5, c0 = blockIdx.y << 5;
#pragma unroll
    for (int i = 0; i < 4; i++) {
        int m = m0 + ty + i * 8;
        sm[ty + i * 8][tx] = Gf[(size_t)m * CB + c0 + tx] * Zr[m];
    }
    __syncthreads();
#pragma unroll
    for (int i = 0; i < 4; i++) {
        int c = c0 + ty + i * 8, m = m0 + tx;
        float v = sm[tx][ty + i * 8];
        __nv_bfloat16 h = __float2bfloat16_rn(v);
        g_Ghi[((size_t)b * CB + c) * NSP + m] = h;
        g_Glo[((size_t)b * CB + c) * NSP + m] = __float2bfloat16_rn(v - __bfloat162float(h));
    }
}

// ---------------------------------------------------------------------------
// Kernel 6: Y(64x128 tile) = expS @ (Gt')^T via mma.sync, K=4096 in 32 chunks
// grid (64 rowtile, NB), 256 thr (8 warps, 16x64 warp tiles)
// ---------------------------------------------------------------------------
__global__ __launch_bounds__(256, 1) void y_mma_kernel()
{
    extern __shared__ __align__(16) char smem[];
    const int tid = threadIdx.x;
    const int wid = tid >> 5, lane = tid & 31;
    const int b = blockIdx.y;
    const int rowBase = blockIdx.x << 6;

    const uint32_t sb = smem_to_u32(smem);
    const int mrow = (wid >> 1) * 16, ncol = (wid & 1) * 64;
    const int aR = lane & 15, aK = (lane >> 4) * 8;
    const int bN = (lane & 7) + ((lane >> 4) << 3), bK = ((lane >> 3) & 1) * 8;

    float acc[8][4];
#pragma unroll
    for (int n = 0; n < 8; n++)
#pragma unroll
        for (int q = 0; q < 4; q++) acc[n][q] = 0.f;

    const int ar = tid >> 2, aseg = tid & 3;
    const int bc = tid >> 1, bhalf = tid & 1;
    const float* Arow = g_S + (size_t)b * NSP * NSP + (size_t)(rowBase + ar) * NSP;
    const __nv_bfloat16* Bh0 = g_Ghi + ((size_t)b * CB + bc) * NSP;
    const __nv_bfloat16* Bl0 = g_Glo + ((size_t)b * CB + bc) * NSP;

    for (int kt = 0; kt < 32; kt++) {
        int kg = kt << 7;
        // A: expS fp32 -> hi/lo bf16 into SMEM
#pragma unroll
        for (int j = 0; j < 8; j++) {
            int k = aseg * 32 + j * 4;
            float4 v = *(const float4*)(Arow + kg + k);
            __nv_bfloat16 hx = __float2bfloat16_rn(v.x), hy = __float2bfloat16_rn(v.y);
            __nv_bfloat16 hz = __float2bfloat16_rn(v.z), hw = __float2bfloat16_rn(v.w);
            __nv_bfloat162 h01(hx, hy), h23(hz, hw);
            __nv_bfloat162 l01(__float2bfloat16_rn(v.x - __bfloat162float(hx)),
                               __float2bfloat16_rn(v.y - __bfloat162float(hy)));
            __nv_bfloat162 l23(__float2bfloat16_rn(v.z - __bfloat162float(hz)),
                               __float2bfloat16_rn(v.w - __bfloat162float(hw)));
            uint32_t so = ar * 272 + k * 2;
            *(uint2*)(smem + Y_AHI + so) = make_uint2(*(uint32_t*)&h01, *(uint32_t*)&h23);
            *(uint2*)(smem + Y_ALO + so) = make_uint2(*(uint32_t*)&l01, *(uint32_t*)&l23);
        }
        // B: Gt' hi/lo copy
#pragma unroll
        for (int j = 0; j < 8; j++) {
            int k = bhalf * 64 + j * 8;
            uint32_t so = bc * 272 + k * 2;
            *(uint4*)(smem + Y_BHI + so) = *(const uint4*)(Bh0 + kg + k);
            *(uint4*)(smem + Y_BLO + so) = *(const uint4*)(Bl0 + kg + k);
        }
        __syncthreads();
#pragma unroll
        for (int ks = 0; ks < 8; ks++) {
            int k0 = ks * 16;
            uint32_t ahi[4], alo[4];
            uint32_t ad = sb + Y_AHI + (mrow + aR) * 272 + (k0 + aK) * 2;
            ldsm4(ahi, ad);
            ldsm4(alo, ad + (Y_ALO - Y_AHI));
#pragma unroll
            for (int nj = 0; nj < 4; nj++) {
                uint32_t bhi[4], blo[4];
                uint32_t bd = sb + Y_BHI + (ncol + nj * 16 + bN) * 272 + (k0 + bK) * 2;
                ldsm4(bhi, bd);
                ldsm4(blo, bd + (Y_BLO - Y_BHI));
                mma16816(acc[nj * 2],     ahi, bhi[0], bhi[1]);
                mma16816(acc[nj * 2 + 1], ahi, bhi[2], bhi[3]);
                mma16816(acc[nj * 2],     ahi, blo[0], blo[1]);
                mma16816(acc[nj * 2 + 1], ahi, blo[2], blo[3]);
                mma16816(acc[nj * 2],     alo, bhi[0], bhi[1]);
                mma16816(acc[nj * 2 + 1], alo, bhi[2], bhi[3]);
            }
        }
        __syncthreads();
    }

    const int g = lane >> 2, tig = lane & 3;
#pragma unroll
    for (int rr = 0; rr < 2; rr++) {
        int row = rowBase + mrow + g + rr * 8;
        float* yrow = g_Y + ((size_t)b * NSP + row) * CB;
#pragma unroll
        for (int ni = 0; ni < 8; ni++) {
            int col = ncol + ni * 8 + tig * 2;
            *(float2*)(yrow + col) = make_float2(acc[ni][rr * 2], acc[ni][rr * 2 + 1]);
        }
    }
}

// ---------------------------------------------------------------------------
// Kernel 7: Out = W_w @ Yview + W_b + x (SIMT FFMA2). grid (32,2,NB)
// ---------------------------------------------------------------------------
__global__ __launch_bounds__(256, 2) void out_kernel(
    const float* __restrict__ x,
    const float* __restrict__ Ww, const float* __restrict__ Wb,
    float* __restrict__ out)
{
    int b = blockIdx.z;
    const float* Byc = g_Y + (size_t)b * CB * NSP;   // (128,4096) flat view, ld=4096
    const float* xb  = x + (size_t)b * CIN * NSP;
    float* Cb_ = out + (size_t)b * CIN * NSP;

    __shared__ __align__(16) float As[8][132];
    __shared__ __align__(16) float Bs[8][128];
    int tid  = threadIdx.x;
    int aRow = tid >> 1, aCol = (tid & 1) << 2;
    int bRow = tid >> 5, bCol = (tid & 31) << 2;
    int ty = tid >> 4, tx = tid & 15;
    int rowBase = blockIdx.y << 7;
    int colBase = blockIdx.x << 7;

    u64 acc[8][4];
#pragma unroll
    for (int i = 0; i < 8; i++)
#pragma unroll
        for (int jp = 0; jp < 4; jp++) acc[i][jp] = pk2(0.f, 0.f);

    for (int k0 = 0; k0 < CB; k0 += 8) {
        float4 av = *(const float4*)(Ww + (size_t)(rowBase + aRow) * CB + k0 + aCol);
        As[aCol + 0][aRow] = av.x;
        As[aCol + 1][aRow] = av.y;
        As[aCol + 2][aRow] = av.z;
        As[aCol + 3][aRow] = av.w;
        *(float4*)&Bs[bRow][bCol] =
            *(const float4*)(Byc + (size_t)(k0 + bRow) * NSP + colBase + bCol);
        __syncthreads();
#pragma unroll
        for (int k = 0; k < 8; k++) {
            float ra[8];
            *(float4*)(ra)     = *(const float4*)&As[k][ty << 2];
            *(float4*)(ra + 4) = *(const float4*)&As[k][64 + (ty << 2)];
            const u64* bp0 = (const u64*)&Bs[k][tx << 2];
            const u64* bp1 = (const u64*)&Bs[k][64 + (tx << 2)];
            u64 rb[4] = {bp0[0], bp0[1], bp1[0], bp1[1]};
#pragma unroll
            for (int i = 0; i < 8; i++) {
                u64 aa = pk2(ra[i], ra[i]);
#pragma unroll
                for (int jp = 0; jp < 4; jp++)
                    acc[i][jp] = fma2(aa, rb[jp], acc[i][jp]);
            }
        }
        __syncthreads();
    }
#pragma unroll
    for (int i = 0; i < 8; i++) {
        int row = rowBase + ((i >> 2) << 6) + (ty << 2) + (i & 3);
        float bv = Wb[row];
#pragma unroll
        for (int jh = 0; jh < 2; jh++) {
            int col = colBase + (jh << 6) + (tx << 2);
            float4 xv = *(const float4*)(xb + (size_t)row * NSP + col);
            float4 v;
            upk2(acc[i][2 * jh],     v.x, v.y);
            upk2(acc[i][2 * jh + 1], v.z, v.w);
            v.x += bv + xv.x; v.y += bv + xv.y;
            v.z += bv + xv.z; v.w += bv + xv.w;
            *(float4*)(Cb_ + (size_t)row * NSP + col) = v;
        }
    }
}

// ---------------------------------------------------------------------------
extern "C" void kernel_launch(void* const* d_in, const int* in_sizes, int n_in,
                              void* d_out, int out_size)
{
    const float* x  = (const float*)d_in[0];
    const float* tw = (const float*)d_in[1];
    const float* tb = (const float*)d_in[2];
    const float* pw = (const float*)d_in[3];
    const float* pb = (const float*)d_in[4];
    const float* gw = (const float*)d_in[5];
    const float* gb = (const float*)d_in[6];
    const float* Ww = (const float*)d_in[7];
    const float* Wb = (const float*)d_in[8];
    float* out = (float*)d_out;

    cudaFuncSetAttribute(scores_mma_kernel, cudaFuncAttributeMaxDynamicSharedMemorySize, SC_BYTES);
    cudaFuncSetAttribute(y_mma_kernel, cudaFuncAttributeMaxDynamicSharedMemorySize, Y_BYTES);

    conv_tpg_kernel<<<dim3(32, 1, 12), 256>>>(x, tw, tb, pw, pb, gw, gb);
    cvtT_kernel<<<2048, 256>>>();
    trP_kernel<<<dim3(128, 4, NB), dim3(32, 8)>>>();
    scores_mma_kernel<<<dim3(32, 32, NB), 256, SC_BYTES>>>();
    zreduce_kernel<<<64, 256>>>();
    gscale_kernel<<<dim3(128, 4, NB), dim3(32, 8)>>>();
    y_mma_kernel<<<dim3(64, NB), 256, Y_BYTES>>>();
    out_kernel<<<dim3(32, 2, NB), 256>>>(x, Ww, Wb, out);
}